// round 1
// baseline (speedup 1.0000x reference)
#include <cuda_runtime.h>
#include <math.h>

#define BB 32
#define NN 512
#define HH 512
#define MTOT (BB*NN)      // 16384 flattened rows for projections
#define KSPLIT 256        // split-K CTAs for final GEMM
#define KCHUNK 1024       // K per split (256*1024 = 262144)

// Scratch (allocation-free rule: __device__ globals)
__device__ float g_q[BB*NN*HH];        // 32 MB
__device__ float g_k[BB*NN*HH];        // 32 MB
__device__ float g_ax[BB*NN*HH];       // 32 MB  (attention @ x)
__device__ float g_part[KSPLIT*BB*HH]; // 16 MB  split-K partials

// ---------------------------------------------------------------------------
// Kernel 1: q/k projections.  C = X @ W + bias
// X [16384,512] row-major, W [512,512] row-major (in,out).
// grid (4, 128, 2): z=0 -> (Wq,bq)->g_q ; z=1 -> (Wk,bk)->g_k
// ---------------------------------------------------------------------------
__global__ __launch_bounds__(256) void proj_kernel(
    const float* __restrict__ X,
    const float* __restrict__ Wq, const float* __restrict__ bq,
    const float* __restrict__ Wk, const float* __restrict__ bk)
{
    const float* W    = blockIdx.z ? Wk : Wq;
    const float* bias = blockIdx.z ? bk : bq;
    float*       C    = blockIdx.z ? g_k : g_q;

    __shared__ float As[16][132];   // A tile transposed [k][m], padded
    __shared__ float Bs[16][128];   // B tile [k][n]

    const int tid = threadIdx.x;
    const int tx = tid & 15, ty = tid >> 4;
    const int row0 = blockIdx.y * 128;
    const int col0 = blockIdx.x * 128;

    float acc[8][8];
    #pragma unroll
    for (int i = 0; i < 8; i++)
        #pragma unroll
        for (int j = 0; j < 8; j++) acc[i][j] = 0.f;

    for (int k0 = 0; k0 < 512; k0 += 16) {
        #pragma unroll
        for (int t = 0; t < 2; t++) {           // A: 128x16 = 512 float4
            int lid = t * 256 + tid;
            int ar = lid >> 2, ac4 = lid & 3;
            float4 v = *reinterpret_cast<const float4*>(
                &X[(size_t)(row0 + ar) * 512 + k0 + ac4 * 4]);
            As[ac4*4+0][ar] = v.x; As[ac4*4+1][ar] = v.y;
            As[ac4*4+2][ar] = v.z; As[ac4*4+3][ar] = v.w;
        }
        #pragma unroll
        for (int t = 0; t < 2; t++) {           // B: 16x128 = 512 float4
            int lid = t * 256 + tid;
            int br = lid >> 5, bc4 = lid & 31;
            float4 v = *reinterpret_cast<const float4*>(
                &W[(size_t)(k0 + br) * 512 + col0 + bc4 * 4]);
            *reinterpret_cast<float4*>(&Bs[br][bc4 * 4]) = v;
        }
        __syncthreads();
        #pragma unroll
        for (int kk = 0; kk < 16; kk++) {
            float a[8], b[8];
            #pragma unroll
            for (int i = 0; i < 8; i++) a[i] = As[kk][ty * 8 + i];
            #pragma unroll
            for (int j = 0; j < 8; j++) b[j] = Bs[kk][tx * 8 + j];
            #pragma unroll
            for (int i = 0; i < 8; i++)
                #pragma unroll
                for (int j = 0; j < 8; j++) acc[i][j] += a[i] * b[j];
        }
        __syncthreads();
    }
    #pragma unroll
    for (int i = 0; i < 8; i++) {
        int r = row0 + ty * 8 + i;
        #pragma unroll
        for (int j = 0; j < 8; j += 4) {
            int c = col0 + tx * 8 + j;
            float4 v;
            v.x = acc[i][j]   + bias[c];
            v.y = acc[i][j+1] + bias[c+1];
            v.z = acc[i][j+2] + bias[c+2];
            v.w = acc[i][j+3] + bias[c+3];
            *reinterpret_cast<float4*>(&C[(size_t)r * 512 + c]) = v;
        }
    }
}

// ---------------------------------------------------------------------------
// Kernel 2: scores (NT GEMM) + sigmoid epilogue.
// S[b,n,m] = sigmoid( (q[b,n,:] . k[b,m,:]) / sqrt(512) ), written to attn.
// grid (4, 4, 32)
// ---------------------------------------------------------------------------
__global__ __launch_bounds__(256) void scores_kernel(float* __restrict__ attn)
{
    const int b = blockIdx.z;
    const float* Q = g_q + (size_t)b * NN * HH;
    const float* K = g_k + (size_t)b * NN * HH;
    float* S = attn + (size_t)b * NN * NN;

    __shared__ float As[16][132];
    __shared__ float Bs[16][132];

    const int tid = threadIdx.x;
    const int tx = tid & 15, ty = tid >> 4;
    const int row0 = blockIdx.y * 128;   // n
    const int col0 = blockIdx.x * 128;   // m

    float acc[8][8];
    #pragma unroll
    for (int i = 0; i < 8; i++)
        #pragma unroll
        for (int j = 0; j < 8; j++) acc[i][j] = 0.f;

    for (int k0 = 0; k0 < 512; k0 += 16) {
        #pragma unroll
        for (int t = 0; t < 2; t++) {
            int lid = t * 256 + tid;
            int ar = lid >> 2, ac4 = lid & 3;
            float4 v = *reinterpret_cast<const float4*>(
                &Q[(size_t)(row0 + ar) * 512 + k0 + ac4 * 4]);
            As[ac4*4+0][ar] = v.x; As[ac4*4+1][ar] = v.y;
            As[ac4*4+2][ar] = v.z; As[ac4*4+3][ar] = v.w;
        }
        #pragma unroll
        for (int t = 0; t < 2; t++) {           // B rows = m, also K-contiguous
            int lid = t * 256 + tid;
            int br = lid >> 2, bc4 = lid & 3;
            float4 v = *reinterpret_cast<const float4*>(
                &K[(size_t)(col0 + br) * 512 + k0 + bc4 * 4]);
            Bs[bc4*4+0][br] = v.x; Bs[bc4*4+1][br] = v.y;
            Bs[bc4*4+2][br] = v.z; Bs[bc4*4+3][br] = v.w;
        }
        __syncthreads();
        #pragma unroll
        for (int kk = 0; kk < 16; kk++) {
            float a[8], bb[8];
            #pragma unroll
            for (int i = 0; i < 8; i++) a[i]  = As[kk][ty * 8 + i];
            #pragma unroll
            for (int j = 0; j < 8; j++) bb[j] = Bs[kk][tx * 8 + j];
            #pragma unroll
            for (int i = 0; i < 8; i++)
                #pragma unroll
                for (int j = 0; j < 8; j++) acc[i][j] += a[i] * bb[j];
        }
        __syncthreads();
    }
    const float scale = 0.04419417382415922f;   // 1/sqrt(512)
    #pragma unroll
    for (int i = 0; i < 8; i++) {
        int r = row0 + ty * 8 + i;
        #pragma unroll
        for (int j = 0; j < 8; j += 4) {
            int c = col0 + tx * 8 + j;
            float4 v;
            v.x = 1.f / (1.f + expf(-acc[i][j]   * scale));
            v.y = 1.f / (1.f + expf(-acc[i][j+1] * scale));
            v.z = 1.f / (1.f + expf(-acc[i][j+2] * scale));
            v.w = 1.f / (1.f + expf(-acc[i][j+3] * scale));
            *reinterpret_cast<float4*>(&S[(size_t)r * 512 + c]) = v;
        }
    }
}

// ---------------------------------------------------------------------------
// Kernel 3: row softmax in-place over 512-wide rows of attn. grid 16384.
// Values are sigmoid outputs in (0,1): no max-subtraction needed.
// ---------------------------------------------------------------------------
__global__ __launch_bounds__(256) void softmax_kernel(float* __restrict__ attn)
{
    float* p = attn + (size_t)blockIdx.x * 512;
    const int tid = threadIdx.x;
    float e0 = expf(p[tid]);
    float e1 = expf(p[tid + 256]);
    float s = e0 + e1;
    #pragma unroll
    for (int o = 16; o > 0; o >>= 1) s += __shfl_xor_sync(0xffffffffu, s, o);
    __shared__ float ws[8];
    if ((tid & 31) == 0) ws[tid >> 5] = s;
    __syncthreads();
    if (tid < 8) {
        float t = ws[tid];
        #pragma unroll
        for (int o = 4; o > 0; o >>= 1) t += __shfl_xor_sync(0xffu, t, o);
        if (tid == 0) ws[0] = t;
    }
    __syncthreads();
    const float inv = 1.f / ws[0];
    p[tid]       = e0 * inv;
    p[tid + 256] = e1 * inv;
}

// ---------------------------------------------------------------------------
// Kernel 4: ax[b] = attn[b] @ x[b]   (batched NN GEMM, 512x512x512)
// grid (4, 4, 32)
// ---------------------------------------------------------------------------
__global__ __launch_bounds__(256) void ax_kernel(
    const float* __restrict__ attn, const float* __restrict__ x)
{
    const int b = blockIdx.z;
    const float* A = attn + (size_t)b * NN * NN;
    const float* X = x    + (size_t)b * NN * HH;
    float*       C = g_ax + (size_t)b * NN * HH;

    __shared__ float As[16][132];
    __shared__ float Bs[16][128];

    const int tid = threadIdx.x;
    const int tx = tid & 15, ty = tid >> 4;
    const int row0 = blockIdx.y * 128;   // n
    const int col0 = blockIdx.x * 128;   // h

    float acc[8][8];
    #pragma unroll
    for (int i = 0; i < 8; i++)
        #pragma unroll
        for (int j = 0; j < 8; j++) acc[i][j] = 0.f;

    for (int k0 = 0; k0 < 512; k0 += 16) {
        #pragma unroll
        for (int t = 0; t < 2; t++) {
            int lid = t * 256 + tid;
            int ar = lid >> 2, ac4 = lid & 3;
            float4 v = *reinterpret_cast<const float4*>(
                &A[(size_t)(row0 + ar) * 512 + k0 + ac4 * 4]);
            As[ac4*4+0][ar] = v.x; As[ac4*4+1][ar] = v.y;
            As[ac4*4+2][ar] = v.z; As[ac4*4+3][ar] = v.w;
        }
        #pragma unroll
        for (int t = 0; t < 2; t++) {
            int lid = t * 256 + tid;
            int br = lid >> 5, bc4 = lid & 31;
            float4 v = *reinterpret_cast<const float4*>(
                &X[(size_t)(k0 + br) * 512 + col0 + bc4 * 4]);
            *reinterpret_cast<float4*>(&Bs[br][bc4 * 4]) = v;
        }
        __syncthreads();
        #pragma unroll
        for (int kk = 0; kk < 16; kk++) {
            float a[8], bb[8];
            #pragma unroll
            for (int i = 0; i < 8; i++) a[i]  = As[kk][ty * 8 + i];
            #pragma unroll
            for (int j = 0; j < 8; j++) bb[j] = Bs[kk][tx * 8 + j];
            #pragma unroll
            for (int i = 0; i < 8; i++)
                #pragma unroll
                for (int j = 0; j < 8; j++) acc[i][j] += a[i] * bb[j];
        }
        __syncthreads();
    }
    #pragma unroll
    for (int i = 0; i < 8; i++) {
        int r = row0 + ty * 8 + i;
        #pragma unroll
        for (int j = 0; j < 8; j += 4) {
            int c = col0 + tx * 8 + j;
            float4 v = make_float4(acc[i][j], acc[i][j+1], acc[i][j+2], acc[i][j+3]);
            *reinterpret_cast<float4*>(&C[(size_t)r * 512 + c]) = v;
        }
    }
}

// ---------------------------------------------------------------------------
// Kernel 5: split-K partials of out = ax.reshape(32, 262144) @ Wm
// grid KSPLIT, each CTA does K chunk of 1024, all M=32, all N=512.
// Deterministic: partials to g_part, reduced in fixed order by kernel 6.
// ---------------------------------------------------------------------------
__global__ __launch_bounds__(256) void final_kernel(const float* __restrict__ Wm)
{
    const int s = blockIdx.x;
    const int k_base = s * KCHUNK;

    __shared__ float As[8][33];
    __shared__ float Bs[8][512];

    const int tid = threadIdx.x;
    const int tx = tid & 63, ty = tid >> 6;   // tx: 64 col tiles, ty: 4 row tiles

    float acc[8][8];
    #pragma unroll
    for (int i = 0; i < 8; i++)
        #pragma unroll
        for (int j = 0; j < 8; j++) acc[i][j] = 0.f;

    for (int k0 = 0; k0 < KCHUNK; k0 += 8) {
        const int kk = k_base + k0;
        {   // A: 32 rows x 8 k
            int m = tid >> 3, kq = tid & 7;
            As[kq][m] = g_ax[(size_t)m * 262144 + kk + kq];
        }
        #pragma unroll
        for (int t = 0; t < 4; t++) {          // B: 8 k x 512 n = 1024 float4
            int lid = t * 256 + tid;
            int br = lid >> 7, bc4 = lid & 127;
            float4 v = *reinterpret_cast<const float4*>(
                &Wm[(size_t)(kk + br) * 512 + bc4 * 4]);
            *reinterpret_cast<float4*>(&Bs[br][bc4 * 4]) = v;
        }
        __syncthreads();
        #pragma unroll
        for (int q = 0; q < 8; q++) {
            float a[8], bb[8];
            #pragma unroll
            for (int i = 0; i < 8; i++) a[i]  = As[q][ty * 8 + i];
            #pragma unroll
            for (int j = 0; j < 8; j++) bb[j] = Bs[q][tx * 8 + j];
            #pragma unroll
            for (int i = 0; i < 8; i++)
                #pragma unroll
                for (int j = 0; j < 8; j++) acc[i][j] += a[i] * bb[j];
        }
        __syncthreads();
    }
    #pragma unroll
    for (int i = 0; i < 8; i++) {
        int m = ty * 8 + i;
        #pragma unroll
        for (int j = 0; j < 8; j += 4) {
            int n = tx * 8 + j;
            float4 v = make_float4(acc[i][j], acc[i][j+1], acc[i][j+2], acc[i][j+3]);
            *reinterpret_cast<float4*>(
                &g_part[((size_t)s * 32 + m) * 512 + n]) = v;
        }
    }
}

// ---------------------------------------------------------------------------
// Kernel 6: deterministic reduction of split-K partials + bias.
// grid 64 x 256 threads = 16384 output elements.
// ---------------------------------------------------------------------------
__global__ __launch_bounds__(256) void reduce_kernel(
    float* __restrict__ out, const float* __restrict__ bm)
{
    const int idx = blockIdx.x * 256 + threadIdx.x;   // 0..16383
    const int m = idx >> 9, n = idx & 511;
    float sum = bm[n];
    #pragma unroll 8
    for (int s = 0; s < KSPLIT; s++)
        sum += g_part[((size_t)s * 32 + m) * 512 + n];
    out[idx] = sum;
}

// ---------------------------------------------------------------------------
extern "C" void kernel_launch(void* const* d_in, const int* in_sizes, int n_in,
                              void* d_out, int out_size)
{
    const float* x  = (const float*)d_in[0];
    const float* Wq = (const float*)d_in[1];
    const float* bq = (const float*)d_in[2];
    const float* Wk = (const float*)d_in[3];
    const float* bk = (const float*)d_in[4];
    const float* Wm = (const float*)d_in[5];
    const float* bm = (const float*)d_in[6];

    float* out  = (float*)d_out;          // [32, 512]
    float* attn = out + 32 * 512;         // [32, 512, 512]

    proj_kernel   <<<dim3(4, 128, 2), 256>>>(x, Wq, bq, Wk, bk);
    scores_kernel <<<dim3(4, 4, 32),  256>>>(attn);
    softmax_kernel<<<16384,           256>>>(attn);
    ax_kernel     <<<dim3(4, 4, 32),  256>>>(attn, x);
    final_kernel  <<<KSPLIT,          256>>>(Wm);
    reduce_kernel <<<64,              256>>>(out, bm);
}